// round 2
// baseline (speedup 1.0000x reference)
#include <cuda_runtime.h>

// Problem shape (fixed by the dataset problem)
constexpr int Bsz = 64;    // batch
constexpr int Qn  = 512;   // query steps
constexpr int Sn  = 1024;  // key sequence
constexpr int Dn  = 1024;  // feature dim

// ---------------------------------------------------------------------------
// Kernel 1: batched NT GEMM  scores[b,q,s] = (1/32) * sum_d query[q,b,d]*key[b,s,d]
// query: [Q, B, D]   key: [B, S, D]   out (scores, later attention): [B, Q, S]
// ---------------------------------------------------------------------------
constexpr int BM = 128, BN = 128, BK = 16, TM = 8, TN = 8;

__global__ __launch_bounds__(256) void gemm_scores_kernel(
    const float* __restrict__ query,
    const float* __restrict__ key,
    float* __restrict__ out)
{
    const int b  = blockIdx.z;
    const int q0 = blockIdx.y * BM;
    const int s0 = blockIdx.x * BN;

    __shared__ float As[BK][BM + 4];
    __shared__ float Bs[BK][BN + 4];

    const int tid = threadIdx.x;
    const int tx  = tid & 15;   // 0..15 -> s sub-tile
    const int ty  = tid >> 4;   // 0..15 -> q sub-tile

    float acc[TM][TN];
#pragma unroll
    for (int i = 0; i < TM; i++)
#pragma unroll
        for (int j = 0; j < TN; j++) acc[i][j] = 0.0f;

    // A(q, d) = query[((q0+q)*Bsz + b)*Dn + d]
    const float* Abase = query + ((size_t)q0 * Bsz + b) * Dn;
    // B(s, d) = key[(b*Sn + s0 + s)*Dn + d]
    const float* Bbase = key + ((size_t)b * Sn + s0) * Dn;

    const int lrow = tid >> 2;        // 0..63
    const int lcol = (tid & 3) * 4;   // 0,4,8,12

    for (int kt = 0; kt < Dn; kt += BK) {
#pragma unroll
        for (int r = 0; r < 2; r++) {
            const int row = lrow + r * 64;
            float4 va = *reinterpret_cast<const float4*>(
                Abase + (size_t)row * (size_t)Bsz * Dn + kt + lcol);
            As[lcol + 0][row] = va.x;
            As[lcol + 1][row] = va.y;
            As[lcol + 2][row] = va.z;
            As[lcol + 3][row] = va.w;
            float4 vb = *reinterpret_cast<const float4*>(
                Bbase + (size_t)row * Dn + kt + lcol);
            Bs[lcol + 0][row] = vb.x;
            Bs[lcol + 1][row] = vb.y;
            Bs[lcol + 2][row] = vb.z;
            Bs[lcol + 3][row] = vb.w;
        }
        __syncthreads();

#pragma unroll
        for (int kk = 0; kk < BK; kk++) {
            float a[TM], bb[TN];
#pragma unroll
            for (int i = 0; i < TM; i++) a[i]  = As[kk][ty * TM + i];
#pragma unroll
            for (int j = 0; j < TN; j++) bb[j] = Bs[kk][tx * TN + j];
#pragma unroll
            for (int i = 0; i < TM; i++)
#pragma unroll
                for (int j = 0; j < TN; j++) acc[i][j] = fmaf(a[i], bb[j], acc[i][j]);
        }
        __syncthreads();
    }

    const float scale = 0.03125f;  // 1/sqrt(1024)
#pragma unroll
    for (int i = 0; i < TM; i++) {
        const int q = q0 + ty * TM + i;
        float* orow = out + ((size_t)b * Qn + q) * Sn + s0 + tx * TN;
#pragma unroll
        for (int j4 = 0; j4 < TN; j4 += 4) {
            float4 v;
            v.x = acc[i][j4 + 0] * scale;
            v.y = acc[i][j4 + 1] * scale;
            v.z = acc[i][j4 + 2] * scale;
            v.w = acc[i][j4 + 3] * scale;
            *reinterpret_cast<float4*>(orow + j4) = v;
        }
    }
}

// ---------------------------------------------------------------------------
// Kernel 2: sequential softmax scan over q, per batch b.
//   mod = scores[q] - acc ; masked -> exp = 0 ; attn = exp/sum ; acc += attn
// In-place on the attention region. acc written to state at the end.
// One CTA per b, 256 threads x 4 elements (S=1024). acc lives in registers.
// ---------------------------------------------------------------------------
__global__ __launch_bounds__(256) void scan_softmax_kernel(
    float* __restrict__ att,              // [B, Q, S], holds scores on entry
    const unsigned char* __restrict__ mask,  // [B, S], nonzero = masked
    float* __restrict__ state)            // [B, S]
{
    const int b   = blockIdx.x;
    const int tid = threadIdx.x;
    const int idx = tid * 4;

    __shared__ float red[8];

    uchar4 mk = *reinterpret_cast<const uchar4*>(mask + (size_t)b * Sn + idx);

    float4 acc = make_float4(0.f, 0.f, 0.f, 0.f);
    float* base = att + (size_t)b * Qn * Sn;

    float4 sc = *reinterpret_cast<const float4*>(base + idx);

    for (int q = 0; q < Qn; q++) {
        // Prefetch next row before the reduction (off the critical path).
        float4 nxt = make_float4(0.f, 0.f, 0.f, 0.f);
        if (q + 1 < Qn)
            nxt = *reinterpret_cast<const float4*>(base + (size_t)(q + 1) * Sn + idx);

        float e0 = mk.x ? 0.0f : __expf(sc.x - acc.x);
        float e1 = mk.y ? 0.0f : __expf(sc.y - acc.y);
        float e2 = mk.z ? 0.0f : __expf(sc.z - acc.z);
        float e3 = mk.w ? 0.0f : __expf(sc.w - acc.w);

        float v = (e0 + e1) + (e2 + e3);
        v += __shfl_xor_sync(0xffffffffu, v, 16);
        v += __shfl_xor_sync(0xffffffffu, v, 8);
        v += __shfl_xor_sync(0xffffffffu, v, 4);
        v += __shfl_xor_sync(0xffffffffu, v, 2);
        v += __shfl_xor_sync(0xffffffffu, v, 1);
        const int lane = tid & 31, wid = tid >> 5;
        if (lane == 0) red[wid] = v;
        __syncthreads();
        float total = ((red[0] + red[1]) + (red[2] + red[3])) +
                      ((red[4] + red[5]) + (red[6] + red[7]));
        __syncthreads();  // protect red[] before next iteration's store

        float inv = __frcp_rn(total);
        float4 at;
        at.x = e0 * inv; at.y = e1 * inv; at.z = e2 * inv; at.w = e3 * inv;

        *reinterpret_cast<float4*>(base + (size_t)q * Sn + idx) = at;

        acc.x += at.x; acc.y += at.y; acc.z += at.z; acc.w += at.w;
        sc = nxt;
    }

    *reinterpret_cast<float4*>(state + (size_t)b * Sn + idx) = acc;
}

// ---------------------------------------------------------------------------
// Launch
// ---------------------------------------------------------------------------
extern "C" void kernel_launch(void* const* d_in, const int* in_sizes, int n_in,
                              void* d_out, int out_size)
{
    const float*         key   = (const float*)d_in[0];          // [B, S, D]
    const float*         query = (const float*)d_in[1];          // [Q, B, D]
    const unsigned char* mask  = (const unsigned char*)d_in[2];  // [B, S] bool

    float* att   = (float*)d_out;                          // [B, Q, S]
    float* state = att + (size_t)Bsz * Qn * Sn;            // [B, S]

    dim3 grid(Sn / BN, Qn / BM, Bsz);
    gemm_scores_kernel<<<grid, 256>>>(query, key, att);
    scan_softmax_kernel<<<Bsz, 256>>>(att, mask, state);
}

// round 7
// speedup vs baseline: 2.9190x; 2.9190x over previous
#include <cuda_runtime.h>
#include <cuda_fp16.h>
#include <cstdint>

constexpr int Bsz = 64, Qn = 512, Sn = 1024, Dn = 1024;

// fp16 copies: query transposed to [B,Q,D], key as [B,S,D]
__device__ __half g_qh[(size_t)Bsz * Qn * Dn];
__device__ __half g_kh[(size_t)Bsz * Sn * Dn];

// ---------------------------------------------------------------------------
// helpers (sm_80-era PTX only — NO 'a'-suffix features, harness targets sm_103)
// ---------------------------------------------------------------------------
__device__ __forceinline__ uint32_t smem_u32(const void* p) {
    uint32_t a;
    asm("{ .reg .u64 t; cvta.to.shared.u64 t, %1; cvt.u32.u64 %0, t; }" : "=r"(a) : "l"(p));
    return a;
}

#define CP16(dst, src) \
    asm volatile("cp.async.cg.shared.global [%0], [%1], 16;" :: "r"(dst), "l"(src) : "memory")
#define CP_COMMIT() asm volatile("cp.async.commit_group;" ::: "memory")
#define CP_WAIT(n)  asm volatile("cp.async.wait_group %0;" :: "n"(n) : "memory")

#define LDSM4(r0, r1, r2, r3, addr)                                        \
    asm volatile("ldmatrix.sync.aligned.m8n8.x4.shared.b16 {%0,%1,%2,%3}, [%4];" \
        : "=r"(r0), "=r"(r1), "=r"(r2), "=r"(r3) : "r"(addr))

#define MMA16816(d, a, b0, b1)                                             \
    asm volatile("mma.sync.aligned.m16n8k16.row.col.f32.f16.f16.f32 "      \
        "{%0,%1,%2,%3}, {%4,%5,%6,%7}, {%8,%9}, {%0,%1,%2,%3};"            \
        : "+f"((d)[0]), "+f"((d)[1]), "+f"((d)[2]), "+f"((d)[3])           \
        : "r"((a)[0]), "r"((a)[1]), "r"((a)[2]), "r"((a)[3]),              \
          "r"(b0), "r"(b1))

// ---------------------------------------------------------------------------
// Convert kernels: fp32 -> fp16
// ---------------------------------------------------------------------------
struct alignas(8) Half4 { __half2 a, b; };

__global__ void convert_key_kernel(const float* __restrict__ in,
                                   __half* __restrict__ out, int n4) {
    int i = blockIdx.x * blockDim.x + threadIdx.x;
    int stride = gridDim.x * blockDim.x;
    for (; i < n4; i += stride) {
        float4 v = reinterpret_cast<const float4*>(in)[i];
        Half4 h;
        h.a = __floats2half2_rn(v.x, v.y);
        h.b = __floats2half2_rn(v.z, v.w);
        reinterpret_cast<Half4*>(out)[i] = h;
    }
}

// query [Q,B,D] fp32 -> [B,Q,D] fp16
__global__ void convert_query_kernel(const float* __restrict__ in,
                                     __half* __restrict__ out, int n4) {
    int i = blockIdx.x * blockDim.x + threadIdx.x;
    int stride = gridDim.x * blockDim.x;
    for (; i < n4; i += stride) {
        int d4  = i & (Dn / 4 - 1);
        int row = i >> 8;             // q*Bsz + b
        int b = row & (Bsz - 1);
        int q = row >> 6;
        float4 v = reinterpret_cast<const float4*>(in)[i];
        Half4 h;
        h.a = __floats2half2_rn(v.x, v.y);
        h.b = __floats2half2_rn(v.z, v.w);
        reinterpret_cast<Half4*>(out)[(size_t)(b * Qn + q) * (Dn / 4) + d4] = h;
    }
}

// ---------------------------------------------------------------------------
// fp16 HMMA GEMM: out[b,q,s] = (1/32) * sum_d qh[b,q,d] * kh[b,s,d]
// 128x128 tile, BK=64 halves (128B rows, SW128 swizzle), cp.async 3-stage.
// ---------------------------------------------------------------------------
constexpr int BM = 128, BN = 128, BKh = 64;
constexpr int NCH = Dn / BKh;             // 16
constexpr int A_BYTES  = BM * 128;        // 16 KB
constexpr int STAGE_B  = 2 * A_BYTES;     // 32 KB (A + B)
constexpr int STAGES   = 3;
constexpr int DYN_SMEM = STAGES * STAGE_B + 1024;   // 97.25 KB

__device__ __forceinline__ void prefetch(uint32_t stBase,
                                         const __half* __restrict__ Ag,
                                         const __half* __restrict__ Bg,
                                         int kt, int tid)
{
    const uint32_t stA = stBase, stB = stBase + A_BYTES;
#pragma unroll
    for (int i = 0; i < 4; i++) {
        int idx = tid * 4 + i;            // 0..1023
        int row = idx >> 3, c = idx & 7;  // row 0..127, 16B-chunk 0..7
        uint32_t so = (uint32_t)(row * 128 + ((c * 16) ^ ((row & 7) * 16)));
        size_t go = (size_t)row * Dn + kt + c * 8;
        CP16(stA + so, Ag + go);
        CP16(stB + so, Bg + go);
    }
    CP_COMMIT();
}

__global__ __launch_bounds__(256, 2) void gemm_hmma_kernel(float* __restrict__ out)
{
    extern __shared__ char dsm[];
    const uint32_t raw = smem_u32(dsm);
    const uint32_t sb  = (raw + 1023) & ~1023u;   // 1KB-align for swizzle
    char* alig = dsm + (sb - raw);

    const int tid  = threadIdx.x;
    const int wid  = tid >> 5, lane = tid & 31;
    const int b    = blockIdx.z;
    const int q0   = blockIdx.y * BM;
    const int s0   = blockIdx.x * BN;

    // warp tile 64(M) x 32(N): 2 x 4 warp grid
    const int m0w = (wid & 1) * 64;
    const int n0w = (wid >> 1) * 32;

    const __half* Ag = g_qh + ((size_t)b * Qn + q0) * Dn;
    const __half* Bg = g_kh + ((size_t)b * Sn + s0) * Dn;

    float acc[4][4][4];
#pragma unroll
    for (int i = 0; i < 4; i++)
#pragma unroll
        for (int j = 0; j < 4; j++)
#pragma unroll
            for (int k = 0; k < 4; k++) acc[i][j][k] = 0.0f;

    // per-lane invariants for ldmatrix addressing
    const int r8    = lane & 7;                       // swizzle row bits
    const int rowA  = m0w + r8 + 8 * ((lane >> 3) & 1);   // + mi*16
    const int khA   = 16 * (lane >> 4);               // k-byte half-select (A)
    const int rowB  = n0w + r8 + 8 * (lane >> 4);     // + g*16
    const int khB   = 16 * ((lane >> 3) & 1);         // k-byte half-select (B)
    const int swz   = r8 * 16;

    prefetch(sb + 0 * STAGE_B, Ag, Bg, 0, tid);
    prefetch(sb + 1 * STAGE_B, Ag, Bg, BKh, tid);

    for (int c = 0; c < NCH; c++) {
        if (c < NCH - 1) { CP_WAIT(1); } else { CP_WAIT(0); }
        __syncthreads();

        if (c + 2 < NCH)
            prefetch(sb + ((c + 2) % STAGES) * STAGE_B, Ag, Bg, (c + 2) * BKh, tid);

        const uint32_t stA = sb + (c % STAGES) * STAGE_B;
        const uint32_t stB = stA + A_BYTES;

#pragma unroll
        for (int ks = 0; ks < 4; ks++) {
            uint32_t a[4][4], bf[2][4];
            const int kbA = (32 * ks + khA) ^ swz;
            const int kbB = (32 * ks + khB) ^ swz;
#pragma unroll
            for (int mi = 0; mi < 4; mi++)
                LDSM4(a[mi][0], a[mi][1], a[mi][2], a[mi][3],
                      stA + (uint32_t)((rowA + mi * 16) * 128 + kbA));
#pragma unroll
            for (int g = 0; g < 2; g++)
                LDSM4(bf[g][0], bf[g][1], bf[g][2], bf[g][3],
                      stB + (uint32_t)((rowB + g * 16) * 128 + kbB));
#pragma unroll
            for (int mi = 0; mi < 4; mi++)
#pragma unroll
                for (int nt = 0; nt < 4; nt++) {
                    const int g = nt >> 1, s2 = (nt & 1) * 2;
                    MMA16816(acc[mi][nt], a[mi], bf[g][s2], bf[g][s2 + 1]);
                }
        }
    }
    __syncthreads();

    // Epilogue: regs -> smem (pitch 132 floats) -> coalesced gmem, scale 1/32
    float* ep = reinterpret_cast<float*>(alig);
    const float scale = 0.03125f;
    const int er = lane >> 2, ec = 2 * (lane & 3);
#pragma unroll
    for (int mi = 0; mi < 4; mi++) {
        const int row0 = m0w + mi * 16 + er;
#pragma unroll
        for (int nt = 0; nt < 4; nt++) {
            const int col = n0w + nt * 8 + ec;
            float2 lo = make_float2(acc[mi][nt][0] * scale, acc[mi][nt][1] * scale);
            float2 hi = make_float2(acc[mi][nt][2] * scale, acc[mi][nt][3] * scale);
            *reinterpret_cast<float2*>(&ep[row0 * 132 + col]) = lo;
            *reinterpret_cast<float2*>(&ep[(row0 + 8) * 132 + col]) = hi;
        }
    }
    __syncthreads();

    float* obase = out + ((size_t)b * Qn + q0) * Sn + s0;
#pragma unroll 4
    for (int i = tid; i < BM * (BN / 4); i += 256) {
        int row = i >> 5, c4 = (i & 31) * 4;
        *reinterpret_cast<float4*>(obase + (size_t)row * Sn + c4) =
            *reinterpret_cast<const float4*>(&ep[row * 132 + c4]);
    }
}

// ---------------------------------------------------------------------------
// Sequential softmax scan (unchanged)
// ---------------------------------------------------------------------------
__global__ __launch_bounds__(256) void scan_softmax_kernel(
    float* __restrict__ att, const unsigned char* __restrict__ mask,
    float* __restrict__ state)
{
    const int b = blockIdx.x;
    const int tid = threadIdx.x;
    const int idx = tid * 4;
    __shared__ float red[8];

    uchar4 mk = *reinterpret_cast<const uchar4*>(mask + (size_t)b * Sn + idx);
    float4 acc = make_float4(0.f, 0.f, 0.f, 0.f);
    float* base = att + (size_t)b * Qn * Sn;
    float4 sc = *reinterpret_cast<const float4*>(base + idx);

    for (int q = 0; q < Qn; q++) {
        float4 nxt = make_float4(0.f, 0.f, 0.f, 0.f);
        if (q + 1 < Qn)
            nxt = *reinterpret_cast<const float4*>(base + (size_t)(q + 1) * Sn + idx);

        float e0 = mk.x ? 0.0f : __expf(sc.x - acc.x);
        float e1 = mk.y ? 0.0f : __expf(sc.y - acc.y);
        float e2 = mk.z ? 0.0f : __expf(sc.z - acc.z);
        float e3 = mk.w ? 0.0f : __expf(sc.w - acc.w);

        float v = (e0 + e1) + (e2 + e3);
        v += __shfl_xor_sync(0xffffffffu, v, 16);
        v += __shfl_xor_sync(0xffffffffu, v, 8);
        v += __shfl_xor_sync(0xffffffffu, v, 4);
        v += __shfl_xor_sync(0xffffffffu, v, 2);
        v += __shfl_xor_sync(0xffffffffu, v, 1);
        const int lane = tid & 31, w = tid >> 5;
        if (lane == 0) red[w] = v;
        __syncthreads();
        float total = ((red[0] + red[1]) + (red[2] + red[3])) +
                      ((red[4] + red[5]) + (red[6] + red[7]));
        __syncthreads();

        float inv = __frcp_rn(total);
        float4 at;
        at.x = e0 * inv; at.y = e1 * inv; at.z = e2 * inv; at.w = e3 * inv;
        *reinterpret_cast<float4*>(base + (size_t)q * Sn + idx) = at;
        acc.x += at.x; acc.y += at.y; acc.z += at.z; acc.w += at.w;
        sc = nxt;
    }
    *reinterpret_cast<float4*>(state + (size_t)b * Sn + idx) = acc;
}

// ---------------------------------------------------------------------------
// Launch
// ---------------------------------------------------------------------------
extern "C" void kernel_launch(void* const* d_in, const int* in_sizes, int n_in,
                              void* d_out, int out_size)
{
    const float*         key   = (const float*)d_in[0];          // [B, S, D]
    const float*         query = (const float*)d_in[1];          // [Q, B, D]
    const unsigned char* mask  = (const unsigned char*)d_in[2];  // [B, S]

    float* att   = (float*)d_out;                      // [B, Q, S]
    float* state = att + (size_t)Bsz * Qn * Sn;        // [B, S]

    cudaFuncSetAttribute(gemm_hmma_kernel,
                         cudaFuncAttributeMaxDynamicSharedMemorySize, DYN_SMEM);

    __half *qh, *kh;
    cudaGetSymbolAddress((void**)&qh, g_qh);
    cudaGetSymbolAddress((void**)&kh, g_kh);

    convert_key_kernel<<<8192, 256>>>(key, kh, Bsz * Sn * Dn / 4);
    convert_query_kernel<<<8192, 256>>>(query, qh, Qn * Bsz * Dn / 4);

    dim3 grid(Sn / BN, Qn / BM, Bsz);
    gemm_hmma_kernel<<<grid, 256, DYN_SMEM>>>(att);
    scan_softmax_kernel<<<Bsz, 256>>>(att, mask, state);
}

// round 8
// speedup vs baseline: 3.6379x; 1.2463x over previous
#include <cuda_runtime.h>
#include <cuda_fp16.h>
#include <cstdint>

constexpr int Bsz = 64, Qn = 512, Sn = 1024, Dn = 1024;

// fp16 copies: query transposed to [B,Q,D], key as [B,S,D]
__device__ __half g_qh[(size_t)Bsz * Qn * Dn];
__device__ __half g_kh[(size_t)Bsz * Sn * Dn];

// producer->consumer flags: one per (b, qblock), 8 s-tile producers each
__device__ int g_flags[256];

// ---------------------------------------------------------------------------
// helpers (sm_80-era PTX only — harness ptxas targets plain sm_103)
// ---------------------------------------------------------------------------
__device__ __forceinline__ uint32_t smem_u32(const void* p) {
    uint32_t a;
    asm("{ .reg .u64 t; cvta.to.shared.u64 t, %1; cvt.u32.u64 %0, t; }" : "=r"(a) : "l"(p));
    return a;
}

#define CP16(dst, src) \
    asm volatile("cp.async.cg.shared.global [%0], [%1], 16;" :: "r"(dst), "l"(src) : "memory")
#define CP_COMMIT() asm volatile("cp.async.commit_group;" ::: "memory")
#define CP_WAIT(n)  asm volatile("cp.async.wait_group %0;" :: "n"(n) : "memory")

#define LDSM4(r0, r1, r2, r3, addr)                                        \
    asm volatile("ldmatrix.sync.aligned.m8n8.x4.shared.b16 {%0,%1,%2,%3}, [%4];" \
        : "=r"(r0), "=r"(r1), "=r"(r2), "=r"(r3) : "r"(addr))

#define MMA16816(d, a, b0, b1)                                             \
    asm volatile("mma.sync.aligned.m16n8k16.row.col.f32.f16.f16.f32 "      \
        "{%0,%1,%2,%3}, {%4,%5,%6,%7}, {%8,%9}, {%0,%1,%2,%3};"            \
        : "+f"((d)[0]), "+f"((d)[1]), "+f"((d)[2]), "+f"((d)[3])           \
        : "r"((a)[0]), "r"((a)[1]), "r"((a)[2]), "r"((a)[3]),              \
          "r"(b0), "r"(b1))

// ---------------------------------------------------------------------------
// Convert kernels: fp32 -> fp16 (key kernel also resets the flags)
// ---------------------------------------------------------------------------
struct alignas(8) Half4 { __half2 a, b; };

__global__ void convert_key_kernel(const float* __restrict__ in,
                                   __half* __restrict__ out, int n4) {
    if (blockIdx.x == 0 && threadIdx.x < 256) g_flags[threadIdx.x] = 0;
    int i = blockIdx.x * blockDim.x + threadIdx.x;
    int stride = gridDim.x * blockDim.x;
    for (; i < n4; i += stride) {
        float4 v = reinterpret_cast<const float4*>(in)[i];
        Half4 h;
        h.a = __floats2half2_rn(v.x, v.y);
        h.b = __floats2half2_rn(v.z, v.w);
        reinterpret_cast<Half4*>(out)[i] = h;
    }
}

// query [Q,B,D] fp32 -> [B,Q,D] fp16
__global__ void convert_query_kernel(const float* __restrict__ in,
                                     __half* __restrict__ out, int n4) {
    int i = blockIdx.x * blockDim.x + threadIdx.x;
    int stride = gridDim.x * blockDim.x;
    for (; i < n4; i += stride) {
        int d4  = i & (Dn / 4 - 1);
        int row = i >> 8;             // q*Bsz + b
        int b = row & (Bsz - 1);
        int q = row >> 6;
        float4 v = reinterpret_cast<const float4*>(in)[i];
        Half4 h;
        h.a = __floats2half2_rn(v.x, v.y);
        h.b = __floats2half2_rn(v.z, v.w);
        reinterpret_cast<Half4*>(out)[(size_t)(b * Qn + q) * (Dn / 4) + d4] = h;
    }
}

// ---------------------------------------------------------------------------
// Fused kernel: blockIdx 0..63 = softmax-scan consumers (one per b),
//               blockIdx 64..2111 = HMMA GEMM producers (q-block outermost).
// ---------------------------------------------------------------------------
constexpr int BM = 128, BN = 128, BKh = 64;
constexpr int NCH = Dn / BKh;             // 16
constexpr int A_BYTES  = BM * 128;        // 16 KB
constexpr int STAGE_B  = 2 * A_BYTES;     // 32 KB
constexpr int STAGES   = 3;
constexpr int DYN_SMEM = STAGES * STAGE_B + 1024;
constexpr int N_SCAN   = Bsz;             // 64
constexpr int N_GEMM   = 4 * Bsz * 8;     // 2048
constexpr int QBLK = 128;

__device__ __forceinline__ void prefetch(uint32_t stBase,
                                         const __half* __restrict__ Ag,
                                         const __half* __restrict__ Bg,
                                         int kt, int tid)
{
    const uint32_t stA = stBase, stB = stBase + A_BYTES;
#pragma unroll
    for (int i = 0; i < 4; i++) {
        int idx = tid * 4 + i;            // 0..1023
        int row = idx >> 3, c = idx & 7;
        uint32_t so = (uint32_t)(row * 128 + ((c * 16) ^ ((row & 7) * 16)));
        size_t go = (size_t)row * Dn + kt + c * 8;
        CP16(stA + so, Ag + go);
        CP16(stB + so, Bg + go);
    }
    CP_COMMIT();
}

__device__ __forceinline__ void gemm_body(float* __restrict__ out, char* dsm)
{
    const uint32_t raw = smem_u32(dsm);
    const uint32_t sb  = (raw + 1023) & ~1023u;
    char* alig = dsm + (sb - raw);

    const int tid  = threadIdx.x;
    const int wid  = tid >> 5, lane = tid & 31;

    const int g    = blockIdx.x - N_SCAN;
    const int qblk = g >> 9;              // 0..3, outermost -> early q first
    const int rem  = g & 511;
    const int b    = rem >> 3;
    const int s0   = (rem & 7) * BN;
    const int q0   = qblk * BM;

    const int m0w = (wid & 1) * 64;
    const int n0w = (wid >> 1) * 32;

    const __half* Ag = g_qh + ((size_t)b * Qn + q0) * Dn;
    const __half* Bg = g_kh + ((size_t)b * Sn + s0) * Dn;

    float acc[4][4][4];
#pragma unroll
    for (int i = 0; i < 4; i++)
#pragma unroll
        for (int j = 0; j < 4; j++)
#pragma unroll
            for (int k = 0; k < 4; k++) acc[i][j][k] = 0.0f;

    const int r8    = lane & 7;
    const int rowA  = m0w + r8 + 8 * ((lane >> 3) & 1);
    const int khA   = 16 * (lane >> 4);
    const int rowB  = n0w + r8 + 8 * (lane >> 4);
    const int khB   = 16 * ((lane >> 3) & 1);
    const int swz   = r8 * 16;

    prefetch(sb + 0 * STAGE_B, Ag, Bg, 0, tid);
    prefetch(sb + 1 * STAGE_B, Ag, Bg, BKh, tid);

    for (int c = 0; c < NCH; c++) {
        if (c < NCH - 1) { CP_WAIT(1); } else { CP_WAIT(0); }
        __syncthreads();

        if (c + 2 < NCH)
            prefetch(sb + ((c + 2) % STAGES) * STAGE_B, Ag, Bg, (c + 2) * BKh, tid);

        const uint32_t stA = sb + (c % STAGES) * STAGE_B;
        const uint32_t stB = stA + A_BYTES;

#pragma unroll
        for (int ks = 0; ks < 4; ks++) {
            uint32_t a[4][4], bf[2][4];
            const int kbA = (32 * ks + khA) ^ swz;
            const int kbB = (32 * ks + khB) ^ swz;
#pragma unroll
            for (int mi = 0; mi < 4; mi++)
                LDSM4(a[mi][0], a[mi][1], a[mi][2], a[mi][3],
                      stA + (uint32_t)((rowA + mi * 16) * 128 + kbA));
#pragma unroll
            for (int gg = 0; gg < 2; gg++)
                LDSM4(bf[gg][0], bf[gg][1], bf[gg][2], bf[gg][3],
                      stB + (uint32_t)((rowB + gg * 16) * 128 + kbB));
#pragma unroll
            for (int mi = 0; mi < 4; mi++)
#pragma unroll
                for (int nt = 0; nt < 4; nt++) {
                    const int gg = nt >> 1, s2 = (nt & 1) * 2;
                    MMA16816(acc[mi][nt], a[mi], bf[gg][s2], bf[gg][s2 + 1]);
                }
        }
    }
    __syncthreads();

    // Epilogue: regs -> smem -> coalesced gmem, scale 1/32
    float* ep = reinterpret_cast<float*>(alig);
    const float scale = 0.03125f;
    const int er = lane >> 2, ec = 2 * (lane & 3);
#pragma unroll
    for (int mi = 0; mi < 4; mi++) {
        const int row0 = m0w + mi * 16 + er;
#pragma unroll
        for (int nt = 0; nt < 4; nt++) {
            const int col = n0w + nt * 8 + ec;
            float2 lo = make_float2(acc[mi][nt][0] * scale, acc[mi][nt][1] * scale);
            float2 hi = make_float2(acc[mi][nt][2] * scale, acc[mi][nt][3] * scale);
            *reinterpret_cast<float2*>(&ep[row0 * 132 + col]) = lo;
            *reinterpret_cast<float2*>(&ep[(row0 + 8) * 132 + col]) = hi;
        }
    }
    __syncthreads();

    float* obase = out + ((size_t)b * Qn + q0) * Sn + s0;
#pragma unroll 4
    for (int i = tid; i < BM * (BN / 4); i += 256) {
        int row = i >> 5, c4 = (i & 31) * 4;
        *reinterpret_cast<float4*>(obase + (size_t)row * Sn + c4) =
            *reinterpret_cast<const float4*>(&ep[row * 132 + c4]);
    }

    // Publish: all stores -> fence -> barrier -> one relaxed atomic
    __threadfence();
    __syncthreads();
    if (tid == 0) atomicAdd(&g_flags[b * 4 + qblk], 1);
}

__device__ __forceinline__ void scan_body(float* __restrict__ att,
                                          const unsigned char* __restrict__ mask,
                                          float* __restrict__ state)
{
    const int b   = blockIdx.x;
    const int tid = threadIdx.x;
    const int idx = tid * 4;
    const int lane = tid & 31, w = tid >> 5;
    __shared__ __align__(16) float red[2][8];

    uchar4 mk = *reinterpret_cast<const uchar4*>(mask + (size_t)b * Sn + idx);
    float4 acc = make_float4(0.f, 0.f, 0.f, 0.f);
    float* base = att + (size_t)b * Qn * Sn;

    for (int qb = 0; qb < 4; qb++) {
        // gate on the 8 producer tiles for (b, qb)
        if (tid == 0) {
            const int* fp = &g_flags[b * 4 + qb];
            int v;
            for (;;) {
                asm volatile("ld.acquire.gpu.global.b32 %0, [%1];" : "=r"(v) : "l"(fp));
                if (v >= 8) break;
                __nanosleep(64);
            }
        }
        __syncthreads();

        float4 sc = *reinterpret_cast<const float4*>(base + (size_t)(qb * QBLK) * Sn + idx);
        for (int qi = 0; qi < QBLK; qi++) {
            const int q = qb * QBLK + qi;
            float4 nxt = make_float4(0.f, 0.f, 0.f, 0.f);
            if (qi + 1 < QBLK)
                nxt = *reinterpret_cast<const float4*>(base + (size_t)(q + 1) * Sn + idx);

            float e0 = mk.x ? 0.0f : __expf(sc.x - acc.x);
            float e1 = mk.y ? 0.0f : __expf(sc.y - acc.y);
            float e2 = mk.z ? 0.0f : __expf(sc.z - acc.z);
            float e3 = mk.w ? 0.0f : __expf(sc.w - acc.w);

            float v = (e0 + e1) + (e2 + e3);
            v += __shfl_xor_sync(0xffffffffu, v, 16);
            v += __shfl_xor_sync(0xffffffffu, v, 8);
            v += __shfl_xor_sync(0xffffffffu, v, 4);
            v += __shfl_xor_sync(0xffffffffu, v, 2);
            v += __shfl_xor_sync(0xffffffffu, v, 1);
            if (lane == 0) red[q & 1][w] = v;
            __syncthreads();   // single barrier: double-buffered red[]
            float4 r0 = *reinterpret_cast<const float4*>(&red[q & 1][0]);
            float4 r1 = *reinterpret_cast<const float4*>(&red[q & 1][4]);
            float total = ((r0.x + r0.y) + (r0.z + r0.w)) +
                          ((r1.x + r1.y) + (r1.z + r1.w));

            float inv;
            asm("rcp.approx.f32 %0, %1;" : "=f"(inv) : "f"(total));
            float4 at;
            at.x = e0 * inv; at.y = e1 * inv; at.z = e2 * inv; at.w = e3 * inv;
            *reinterpret_cast<float4*>(base + (size_t)q * Sn + idx) = at;
            acc.x += at.x; acc.y += at.y; acc.z += at.z; acc.w += at.w;
            sc = nxt;
        }
    }
    *reinterpret_cast<float4*>(state + (size_t)b * Sn + idx) = acc;
}

__global__ __launch_bounds__(256, 2) void fused_kernel(
    float* __restrict__ att, const unsigned char* __restrict__ mask,
    float* __restrict__ state)
{
    extern __shared__ char dsm[];
    if (blockIdx.x < N_SCAN) {
        scan_body(att, mask, state);
    } else {
        gemm_body(att, dsm);
    }
}

// ---------------------------------------------------------------------------
// Launch
// ---------------------------------------------------------------------------
extern "C" void kernel_launch(void* const* d_in, const int* in_sizes, int n_in,
                              void* d_out, int out_size)
{
    const float*         key   = (const float*)d_in[0];          // [B, S, D]
    const float*         query = (const float*)d_in[1];          // [Q, B, D]
    const unsigned char* mask  = (const unsigned char*)d_in[2];  // [B, S]

    float* att   = (float*)d_out;                      // [B, Q, S]
    float* state = att + (size_t)Bsz * Qn * Sn;        // [B, S]

    cudaFuncSetAttribute(fused_kernel,
                         cudaFuncAttributeMaxDynamicSharedMemorySize, DYN_SMEM);

    __half *qh, *kh;
    cudaGetSymbolAddress((void**)&qh, g_qh);
    cudaGetSymbolAddress((void**)&kh, g_kh);

    convert_key_kernel<<<8192, 256>>>(key, kh, Bsz * Sn * Dn / 4);
    convert_query_kernel<<<8192, 256>>>(query, qh, Qn * Bsz * Dn / 4);

    fused_kernel<<<N_SCAN + N_GEMM, 256, DYN_SMEM>>>(att, mask, state);
}